// round 12
// baseline (speedup 1.0000x reference)
#include <cuda_runtime.h>
#include <cuda_bf16.h>
#include <math.h>
#include <stdint.h>

#define DD 128

static const int MAXP = 200000;
static const int MAXA = 30000;
static const int MAXS = 50000;
static const int MAXTMP = 110000;
static const int MAXE_TOT = 2000000;
static const int MAXN_TOT = 560000 + 64;

// ---------------- scratch (static __device__, no allocations) ----------------
__device__ float g_xp[MAXP * DD];
__device__ float g_xa[MAXA * DD];
__device__ float g_xs[MAXS * DD];
__device__ float g_yp[MAXP * DD];
__device__ float g_ya[MAXA * DD];
__device__ float g_ys[MAXS * DD];
__device__ float g_agg[MAXP * DD];
__device__ float g_tmp[MAXTMP * DD];
__device__ int g_rowptr[MAXN_TOT];
__device__ int g_cnt[MAXN_TOT];
__device__ int g_cursor[MAXN_TOT];
__device__ int g_srcs[MAXE_TOT];
__device__ int g_part[1024];
// bf16x2 packed hi/lo planes (64 uint32 per row)
__device__ uint32_t g_xhp[MAXP * 64];
__device__ uint32_t g_xlp[MAXP * 64];
__device__ uint32_t g_xha[MAXA * 64];
__device__ uint32_t g_xla[MAXA * 64];
__device__ uint32_t g_xhs[MAXS * 64];
__device__ uint32_t g_xls[MAXS * 64];
__device__ uint32_t g_yhp[MAXP * 64];
__device__ uint32_t g_ylp[MAXP * 64];
__device__ uint32_t g_yha[MAXA * 64];
__device__ uint32_t g_yla[MAXA * 64];
__device__ uint32_t g_yhs[MAXS * 64];
__device__ uint32_t g_yls[MAXS * 64];
__device__ uint32_t g_aggh[MAXP * 64];
__device__ uint32_t g_aggl[MAXP * 64];
// packed weights: per 128x128 matrix -> 64 pair-rows x 128 cols uint32
__device__ uint32_t g_wlh[18 * 8192];
__device__ uint32_t g_wll[18 * 8192];
__device__ uint32_t g_wrh[18 * 8192];
__device__ uint32_t g_wrl[18 * 8192];
__device__ uint32_t g_p1h[3 * 8192];
__device__ uint32_t g_p1l[3 * 8192];
__device__ uint32_t g_p2h[3 * 8192];
__device__ uint32_t g_p2l[3 * 8192];

// ---------------- helpers ----------------
__device__ __forceinline__ float4 ld4(const float* p) { return *reinterpret_cast<const float4*>(p); }
__device__ __forceinline__ void st4(float* p, float4 v) { *reinterpret_cast<float4*>(p) = v; }
__device__ __forceinline__ float2 ld2(const float* p) { return *reinterpret_cast<const float2*>(p); }
__device__ __forceinline__ void st2(float* p, float2 v) { *reinterpret_cast<float2*>(p) = v; }
__device__ __forceinline__ float4 f4add(float4 a, float4 b) {
    return make_float4(a.x + b.x, a.y + b.y, a.z + b.z, a.w + b.w);
}

// pack two floats into bf16x2 (lower16 = first/even-k element)
__device__ __forceinline__ uint32_t pack_bf16x2(float lo_elem, float hi_elem) {
    uint32_t d;
    asm("cvt.rn.bf16x2.f32 %0, %1, %2;" : "=r"(d) : "f"(hi_elem), "f"(lo_elem));
    return d;
}
__device__ __forceinline__ void split_bf16(float a, float& hi, float& lo) {
    __nv_bfloat16 h = __float2bfloat16_rn(a);
    hi = __bfloat162float(h);
    lo = a - hi;
}
// split+pack a k-pair (x = even k, y = odd k)
__device__ __forceinline__ void emit_hl(uint32_t* oh, uint32_t* ol, size_t base, float x, float y) {
    float hx, lx, hy, ly;
    split_bf16(x, hx, lx);
    split_bf16(y, hy, ly);
    oh[base] = pack_bf16x2(hx, hy);
    ol[base] = pack_bf16x2(lx, ly);
}

__device__ __forceinline__ void mma_bf16(float* c, const uint32_t* a, const uint32_t* b) {
    asm volatile(
        "mma.sync.aligned.m16n8k16.row.col.f32.bf16.bf16.f32 "
        "{%0,%1,%2,%3}, {%4,%5,%6,%7}, {%8,%9}, {%0,%1,%2,%3};"
        : "+f"(c[0]), "+f"(c[1]), "+f"(c[2]), "+f"(c[3])
        : "r"(a[0]), "r"(a[1]), "r"(a[2]), "r"(a[3]), "r"(b[0]), "r"(b[1]));
}

__device__ __forceinline__ void cp16(uint32_t* smem_dst, const uint32_t* gsrc) {
    uint32_t saddr = (uint32_t)__cvta_generic_to_shared(smem_dst);
    asm volatile("cp.async.ca.shared.global [%0], [%1], 16;" :: "r"(saddr), "l"(gsrc));
}
#define CP_COMMIT() asm volatile("cp.async.commit_group;")
#define CP_WAIT2() asm volatile("cp.async.wait_group 2;" ::: "memory")

// ---------------- utility kernels ----------------
__global__ void k_zero(int* p, int n) {
    int i = blockIdx.x * blockDim.x + threadIdx.x;
    if (i < n) p[i] = 0;
}

// convert all weight matrices to packed bf16x2 hi/lo (one launch)
__global__ void k_wsplit(const float* __restrict__ Wl, const float* __restrict__ Wr,
                         const float* __restrict__ p1, const float* __restrict__ p2,
                         uint32_t* wlh, uint32_t* wll, uint32_t* wrh, uint32_t* wrl,
                         uint32_t* p1h, uint32_t* p1l, uint32_t* p2h, uint32_t* p2l) {
    int idx = blockIdx.x * blockDim.x + threadIdx.x;
    const int NW = 18 * 8192, NP = 3 * 8192;
    const float* src;
    uint32_t *dh, *dl;
    int j;
    if (idx < NW) { src = Wl; dh = wlh; dl = wll; j = idx; }
    else if (idx < 2 * NW) { src = Wr; dh = wrh; dl = wrl; j = idx - NW; }
    else if (idx < 2 * NW + NP) { src = p1; dh = p1h; dl = p1l; j = idx - 2 * NW; }
    else if (idx < 2 * NW + 2 * NP) { src = p2; dh = p2h; dl = p2l; j = idx - 2 * NW - NP; }
    else return;
    int mat = j >> 13;
    int rem = j & 8191;
    int p = rem >> 7, n = rem & 127;
    float a = src[(size_t)mat * 16384 + (2 * p) * 128 + n];
    float b = src[(size_t)mat * 16384 + (2 * p + 1) * 128 + n];
    float ha, la, hb, lb;
    split_bf16(a, ha, la);
    split_bf16(b, hb, lb);
    dh[j] = pack_bf16x2(ha, hb);
    dl[j] = pack_bf16x2(la, lb);
}

// x[r] = emb[nid[r]]; also emit hi/lo planes
__global__ void k_gather(const float* __restrict__ emb, const int* __restrict__ nid,
                         float* __restrict__ x, uint32_t* __restrict__ xh,
                         uint32_t* __restrict__ xl, int n) {
    int i = blockIdx.x * blockDim.x + threadIdx.x;
    if (i < n * 32) {
        int r = i >> 5, c = i & 31;
        float4 v = ld4(emb + (size_t)nid[r] * DD + c * 4);
        st4(x + (size_t)r * DD + c * 4, v);
        size_t pb = (size_t)r * 64 + c * 2;
        emit_hl(xh, xl, pb, v.x, v.y);
        emit_hl(xh, xl, pb + 1, v.z, v.w);
    }
}

__global__ void k_count(const int* __restrict__ dst, int E, int* cnt) {
    int e = blockIdx.x * blockDim.x + threadIdx.x;
    if (e < E) atomicAdd(&cnt[dst[e]], 1);
}

__global__ void k_scan1(const int* __restrict__ cnt, int* __restrict__ rowptr,
                        int* __restrict__ part, int N) {
    __shared__ int s[512];
    int tid = threadIdx.x;
    int i = blockIdx.x * 512 + tid;
    int v = (i < N) ? cnt[i] : 0;
    s[tid] = v;
    __syncthreads();
    for (int off = 1; off < 512; off <<= 1) {
        int t = (tid >= off) ? s[tid - off] : 0;
        __syncthreads();
        s[tid] += t;
        __syncthreads();
    }
    if (i < N) rowptr[i] = s[tid] - v;
    if (tid == 511) part[blockIdx.x] = s[511];
}

__global__ void k_scan2(int* part, int n) {
    __shared__ int s[512];
    int tid = threadIdx.x;
    int v = (tid < n) ? part[tid] : 0;
    s[tid] = v;
    __syncthreads();
    for (int off = 1; off < 512; off <<= 1) {
        int t = (tid >= off) ? s[tid - off] : 0;
        __syncthreads();
        s[tid] += t;
        __syncthreads();
    }
    if (tid < n) part[tid] = s[tid] - v;
}

__global__ void k_scan3(int* rowptr, const int* __restrict__ part, int N) {
    int i = blockIdx.x * blockDim.x + threadIdx.x;
    if (i < N) rowptr[i] += part[i >> 9];
}

__global__ void k_scatter(const int* __restrict__ src, const int* __restrict__ dst, int E,
                          const int* __restrict__ rowptr, int* __restrict__ cursor,
                          int* __restrict__ out) {
    int e = blockIdx.x * blockDim.x + threadIdx.x;
    if (e < E) {
        int d = dst[e];
        int pos = rowptr[d] + atomicAdd(&cursor[d], 1);
        out[pos] = src[e];
    }
}

// segment-mean gather; optional hi/lo emission (for use as GEMM A operand)
template <bool EMITHL>
__global__ void k_agg(const float* __restrict__ feat, const int* __restrict__ rowptr,
                      const int* __restrict__ cnt, const int* __restrict__ srcs,
                      float* __restrict__ out, uint32_t* __restrict__ oh,
                      uint32_t* __restrict__ ol, int N) {
    int warp = (blockIdx.x * blockDim.x + threadIdx.x) >> 5;
    if (warp >= N) return;
    int lane = threadIdx.x & 31;
    int beg = rowptr[warp], n = cnt[warp];
    float4 acc = make_float4(0.f, 0.f, 0.f, 0.f);
    int i = 0;
    for (; i + 4 <= n; i += 4) {
        int s0 = srcs[beg + i], s1 = srcs[beg + i + 1];
        int s2 = srcs[beg + i + 2], s3 = srcs[beg + i + 3];
        float4 v0 = ld4(feat + (size_t)s0 * DD + lane * 4);
        float4 v1 = ld4(feat + (size_t)s1 * DD + lane * 4);
        float4 v2 = ld4(feat + (size_t)s2 * DD + lane * 4);
        float4 v3 = ld4(feat + (size_t)s3 * DD + lane * 4);
        acc = f4add(acc, f4add(f4add(v0, v1), f4add(v2, v3)));
    }
    for (; i < n; i++) {
        int s = srcs[beg + i];
        acc = f4add(acc, ld4(feat + (size_t)s * DD + lane * 4));
    }
    float inv = 1.0f / (float)max(n, 1);
    acc.x *= inv; acc.y *= inv; acc.z *= inv; acc.w *= inv;
    st4(out + (size_t)warp * DD + lane * 4, acc);
    if constexpr (EMITHL) {
        size_t pb = (size_t)warp * 64 + lane * 2;
        emit_hl(oh, ol, pb, acc.x, acc.y);
        emit_hl(oh, ol, pb + 1, acc.z, acc.w);
    }
}

// layernorm: emits hi/lo planes only (consumed solely as GEMM A operand)
__global__ void k_ln(const float* __restrict__ x, const float* __restrict__ g,
                     const float* __restrict__ b, uint32_t* __restrict__ yh,
                     uint32_t* __restrict__ yl, int N) {
    int warp = (blockIdx.x * blockDim.x + threadIdx.x) >> 5;
    if (warp >= N) return;
    int lane = threadIdx.x & 31;
    float4 v = ld4(x + (size_t)warp * DD + lane * 4);
    float s = v.x + v.y + v.z + v.w;
#pragma unroll
    for (int m = 16; m > 0; m >>= 1) s += __shfl_xor_sync(0xffffffffu, s, m);
    float mu = s * (1.0f / 128.0f);
    float4 d = make_float4(v.x - mu, v.y - mu, v.z - mu, v.w - mu);
    float ss = d.x * d.x + d.y * d.y + d.z * d.z + d.w * d.w;
#pragma unroll
    for (int m = 16; m > 0; m >>= 1) ss += __shfl_xor_sync(0xffffffffu, ss, m);
    float sc = rsqrtf(ss * (1.0f / 128.0f) + 1e-5f);
    float4 gv = ld4(g + lane * 4), bv = ld4(b + lane * 4);
    float4 o = make_float4(d.x * sc * gv.x + bv.x, d.y * sc * gv.y + bv.y,
                           d.z * sc * gv.z + bv.z, d.w * sc * gv.w + bv.w);
    size_t pb = (size_t)warp * 64 + lane * 2;
    emit_hl(yh, yl, pb, o.x, o.y);
    emit_hl(yh, yl, pb + 1, o.z, o.w);
}

// ---------------- tensor-core fused GEMM (pre-split bf16 hi/lo, cp.async 4-stage) -------
// h = (U1 ? A1@W1 : 0) + (U2 ? A2@W2 : 0) + (HASPASS ? pass : 0) + (HASB ? bias : 0)
// EPI: 0 fp32 store; 1 l2norm fp32 store; 2 l2norm add fp32+hl; 3 l2norm add relu fp32+hl;
//      4 relu hl-only store
// Operands: A planes = packed bf16x2 [row][64]; W planes = packed [64 pair-rows][128].
// Block 128x128, 8 warps (2m x 4n), k16 chunks, 4-stage cp.async ring.
static const int GSTAGE = 128 * 12 * 2 + 8 * 136 * 2;  // uint32 per stage = 5248
static const int GSMEM_BYTES = (4 * GSTAGE + 512) * 4; // 86016

template <bool U1, bool U2, bool HASB, bool HASPASS, int EPI>
__global__ void __launch_bounds__(256, 2)
k_gemm(const uint32_t* __restrict__ A1h, const uint32_t* __restrict__ A1l,
       const uint32_t* __restrict__ W1h, const uint32_t* __restrict__ W1l,
       const uint32_t* __restrict__ A2h, const uint32_t* __restrict__ A2l,
       const uint32_t* __restrict__ W2h, const uint32_t* __restrict__ W2l,
       const float* __restrict__ bias, const float* __restrict__ pass,
       float* __restrict__ out, uint32_t* __restrict__ outH, uint32_t* __restrict__ outL,
       int N) {
    extern __shared__ uint32_t smem[];
    float* red = (float*)(smem + 4 * GSTAGE);

    const int tid = threadIdx.x;
    const int warp = tid >> 5;
    const int lane = tid & 31;
    const int warpM = warp >> 2;
    const int warpN = warp & 3;
    const int g = lane >> 2;
    const int t = lane & 3;
    const int row0 = blockIdx.x * 128;

    const int aR = tid >> 1, aS = tid & 1;          // A copy: row, 16B segment
    const int wR = tid >> 5, wS = tid & 31;         // W copy: pair-row, 16B segment
    const int aRow = min(row0 + aR, N - 1);

    const int total = (U1 ? 8 : 0) + (U2 ? 8 : 0);

    auto issue = [&](int k) {
        const uint32_t *Ah, *Al, *Wh, *Wl;
        int kk;
        if (U1 && U2) {
            if (k < 8) { Ah = A1h; Al = A1l; Wh = W1h; Wl = W1l; kk = k; }
            else { Ah = A2h; Al = A2l; Wh = W2h; Wl = W2l; kk = k - 8; }
        } else if (U1) { Ah = A1h; Al = A1l; Wh = W1h; Wl = W1l; kk = k; }
        else { Ah = A2h; Al = A2l; Wh = W2h; Wl = W2l; kk = k; }
        uint32_t* st = smem + (k & 3) * GSTAGE;
        cp16(st + aR * 12 + aS * 4, Ah + (size_t)aRow * 64 + kk * 8 + aS * 4);
        cp16(st + 1536 + aR * 12 + aS * 4, Al + (size_t)aRow * 64 + kk * 8 + aS * 4);
        cp16(st + 3072 + wR * 136 + wS * 4, Wh + (size_t)(kk * 8 + wR) * 128 + wS * 4);
        cp16(st + 4160 + wR * 136 + wS * 4, Wl + (size_t)(kk * 8 + wR) * 128 + wS * 4);
    };

    float Cr[4][4][4];
#pragma unroll
    for (int mt = 0; mt < 4; mt++)
#pragma unroll
        for (int nt = 0; nt < 4; nt++)
#pragma unroll
            for (int j = 0; j < 4; j++) Cr[mt][nt][j] = 0.f;

    // prologue: 3 stages in flight
#pragma unroll
    for (int k = 0; k < 3; k++) {
        if (k < total) issue(k);
        CP_COMMIT();
    }

    for (int c = 0; c < total; c++) {
        CP_WAIT2();
        __syncthreads();
        const uint32_t* st = smem + (c & 3) * GSTAGE;
        const uint32_t* sAh = st;
        const uint32_t* sAl = st + 1536;
        const uint32_t* sWh = st + 3072;
        const uint32_t* sWl = st + 4160;

        uint32_t bHi[4][2], bLo[4][2];
#pragma unroll
        for (int nt = 0; nt < 4; nt++) {
            int n0 = warpN * 32 + nt * 8 + g;
            bHi[nt][0] = sWh[t * 136 + n0];
            bHi[nt][1] = sWh[(t + 4) * 136 + n0];
            bLo[nt][0] = sWl[t * 136 + n0];
            bLo[nt][1] = sWl[(t + 4) * 136 + n0];
        }
#pragma unroll
        for (int mt = 0; mt < 4; mt++) {
            int rb = warpM * 64 + mt * 16 + g;
            uint32_t aHi[4], aLo[4];
            aHi[0] = sAh[rb * 12 + t];
            aHi[1] = sAh[(rb + 8) * 12 + t];
            aHi[2] = sAh[rb * 12 + t + 4];
            aHi[3] = sAh[(rb + 8) * 12 + t + 4];
            aLo[0] = sAl[rb * 12 + t];
            aLo[1] = sAl[(rb + 8) * 12 + t];
            aLo[2] = sAl[rb * 12 + t + 4];
            aLo[3] = sAl[(rb + 8) * 12 + t + 4];
#pragma unroll
            for (int nt = 0; nt < 4; nt++) {
                mma_bf16(Cr[mt][nt], aHi, bHi[nt]);
                mma_bf16(Cr[mt][nt], aLo, bHi[nt]);
                mma_bf16(Cr[mt][nt], aHi, bLo[nt]);
            }
        }
        if (c + 3 < total) issue(c + 3);
        CP_COMMIT();
    }
    __syncthreads();

    // ---- epilogue ----
    float2 bv[4];
    if constexpr (HASB) {
#pragma unroll
        for (int nt = 0; nt < 4; nt++) bv[nt] = ld2(bias + warpN * 32 + nt * 8 + 2 * t);
    }

#pragma unroll
    for (int mt = 0; mt < 4; mt++) {
        int gr0 = row0 + warpM * 64 + mt * 16 + g;
        int gr1 = gr0 + 8;
        bool v0 = gr0 < N, v1 = gr1 < N;
#pragma unroll
        for (int nt = 0; nt < 4; nt++) {
            int col = warpN * 32 + nt * 8 + 2 * t;
            if constexpr (HASPASS) {
                if (v0) {
                    float2 p = ld2(pass + (size_t)gr0 * 128 + col);
                    Cr[mt][nt][0] += p.x; Cr[mt][nt][1] += p.y;
                }
                if (v1) {
                    float2 p = ld2(pass + (size_t)gr1 * 128 + col);
                    Cr[mt][nt][2] += p.x; Cr[mt][nt][3] += p.y;
                }
            }
            if constexpr (HASB) {
                Cr[mt][nt][0] += bv[nt].x; Cr[mt][nt][1] += bv[nt].y;
                Cr[mt][nt][2] += bv[nt].x; Cr[mt][nt][3] += bv[nt].y;
            }
        }
    }

    if constexpr (EPI == 0 || EPI == 4) {
#pragma unroll
        for (int mt = 0; mt < 4; mt++) {
            int gr0 = row0 + warpM * 64 + mt * 16 + g;
            int gr1 = gr0 + 8;
#pragma unroll
            for (int nt = 0; nt < 4; nt++) {
                int col = warpN * 32 + nt * 8 + 2 * t;
                float2 u0 = make_float2(Cr[mt][nt][0], Cr[mt][nt][1]);
                float2 u1 = make_float2(Cr[mt][nt][2], Cr[mt][nt][3]);
                if constexpr (EPI == 4) {
                    u0.x = fmaxf(u0.x, 0.f); u0.y = fmaxf(u0.y, 0.f);
                    u1.x = fmaxf(u1.x, 0.f); u1.y = fmaxf(u1.y, 0.f);
                    if (gr0 < N) emit_hl(outH, outL, (size_t)gr0 * 64 + (col >> 1), u0.x, u0.y);
                    if (gr1 < N) emit_hl(outH, outL, (size_t)gr1 * 64 + (col >> 1), u1.x, u1.y);
                } else {
                    if (gr0 < N) st2(out + (size_t)gr0 * 128 + col, u0);
                    if (gr1 < N) st2(out + (size_t)gr1 * 128 + col, u1);
                }
            }
        }
    } else {
#pragma unroll
        for (int mt = 0; mt < 4; mt++) {
            float s0 = 0.f, s1 = 0.f;
#pragma unroll
            for (int nt = 0; nt < 4; nt++) {
                s0 += Cr[mt][nt][0] * Cr[mt][nt][0] + Cr[mt][nt][1] * Cr[mt][nt][1];
                s1 += Cr[mt][nt][2] * Cr[mt][nt][2] + Cr[mt][nt][3] * Cr[mt][nt][3];
            }
            s0 += __shfl_xor_sync(0xffffffffu, s0, 1);
            s0 += __shfl_xor_sync(0xffffffffu, s0, 2);
            s1 += __shfl_xor_sync(0xffffffffu, s1, 1);
            s1 += __shfl_xor_sync(0xffffffffu, s1, 2);
            if (t == 0) {
                int lr = warpM * 64 + mt * 16 + g;
                red[warpN * 128 + lr] = s0;
                red[warpN * 128 + lr + 8] = s1;
            }
        }
        __syncthreads();
#pragma unroll
        for (int mt = 0; mt < 4; mt++) {
            int lr0 = warpM * 64 + mt * 16 + g;
            int lr1 = lr0 + 8;
            float q0 = red[lr0] + red[128 + lr0] + red[256 + lr0] + red[384 + lr0];
            float q1 = red[lr1] + red[128 + lr1] + red[256 + lr1] + red[384 + lr1];
            float sc0 = 1.0f / fmaxf(sqrtf(q0), 1e-12f);
            float sc1 = 1.0f / fmaxf(sqrtf(q1), 1e-12f);
            int gr0 = row0 + lr0, gr1 = row0 + lr1;
#pragma unroll
            for (int nt = 0; nt < 4; nt++) {
                int col = warpN * 32 + nt * 8 + 2 * t;
                float2 u0 = make_float2(Cr[mt][nt][0] * sc0, Cr[mt][nt][1] * sc0);
                float2 u1 = make_float2(Cr[mt][nt][2] * sc1, Cr[mt][nt][3] * sc1);
                if constexpr (EPI == 2 || EPI == 3) {
                    if (gr0 < N) {
                        float2 p = ld2(out + (size_t)gr0 * 128 + col);
                        u0.x += p.x; u0.y += p.y;
                    }
                    if (gr1 < N) {
                        float2 p = ld2(out + (size_t)gr1 * 128 + col);
                        u1.x += p.x; u1.y += p.y;
                    }
                    if constexpr (EPI == 3) {
                        u0.x = fmaxf(u0.x, 0.f); u0.y = fmaxf(u0.y, 0.f);
                        u1.x = fmaxf(u1.x, 0.f); u1.y = fmaxf(u1.y, 0.f);
                    }
                }
                if (gr0 < N) {
                    st2(out + (size_t)gr0 * 128 + col, u0);
                    if constexpr (EPI == 2 || EPI == 3)
                        emit_hl(outH, outL, (size_t)gr0 * 64 + (col >> 1), u0.x, u0.y);
                }
                if (gr1 < N) {
                    st2(out + (size_t)gr1 * 128 + col, u1);
                    if constexpr (EPI == 2 || EPI == 3)
                        emit_hl(outH, outL, (size_t)gr1 * 64 + (col >> 1), u1.x, u1.y);
                }
            }
        }
    }
}

// ---------------- host orchestration ----------------
extern "C" void kernel_launch(void* const* d_in, const int* in_sizes, int n_in,
                              void* d_out, int out_size) {
    const int* nidP = (const int*)d_in[0];
    const int* nidA = (const int*)d_in[1];
    const int* nidS = (const int*)d_in[2];
    const int* Eptr[6];
    int Ecnt[6];
    for (int r = 0; r < 6; r++) {
        Eptr[r] = (const int*)d_in[3 + r];
        Ecnt[r] = in_sizes[3 + r] / 2;
    }
    const float* embP = (const float*)d_in[9];
    const float* embA = (const float*)d_in[10];
    const float* embS = (const float*)d_in[11];
    const float* Wl = (const float*)d_in[12];
    const float* bl = (const float*)d_in[13];
    const float* Wr = (const float*)d_in[14];
    const float* lng = (const float*)d_in[15];
    const float* lnb = (const float*)d_in[16];
    const float* pw1 = (const float*)d_in[17];
    const float* pb1 = (const float*)d_in[18];
    const float* pw2 = (const float*)d_in[19];
    const float* pb2 = (const float*)d_in[20];
    int NPn = in_sizes[0], NAn = in_sizes[1], NSn = in_sizes[2];

    float *xp, *xa, *xs, *yp, *ya, *ys, *agg, *tmp;
    int *rowptr, *cnt, *cursor, *srcs, *part;
    uint32_t *xhp, *xlp, *xha, *xla, *xhs, *xls;
    uint32_t *yhp, *ylp, *yha, *yla, *yhs, *yls;
    uint32_t *aggh, *aggl;
    uint32_t *wlh, *wll, *wrh, *wrl, *p1h, *p1l, *p2h, *p2l;
    cudaGetSymbolAddress((void**)&xp, g_xp);
    cudaGetSymbolAddress((void**)&xa, g_xa);
    cudaGetSymbolAddress((void**)&xs, g_xs);
    cudaGetSymbolAddress((void**)&yp, g_yp);
    cudaGetSymbolAddress((void**)&ya, g_ya);
    cudaGetSymbolAddress((void**)&ys, g_ys);
    cudaGetSymbolAddress((void**)&agg, g_agg);
    cudaGetSymbolAddress((void**)&tmp, g_tmp);
    cudaGetSymbolAddress((void**)&rowptr, g_rowptr);
    cudaGetSymbolAddress((void**)&cnt, g_cnt);
    cudaGetSymbolAddress((void**)&cursor, g_cursor);
    cudaGetSymbolAddress((void**)&srcs, g_srcs);
    cudaGetSymbolAddress((void**)&part, g_part);
    cudaGetSymbolAddress((void**)&xhp, g_xhp);
    cudaGetSymbolAddress((void**)&xlp, g_xlp);
    cudaGetSymbolAddress((void**)&xha, g_xha);
    cudaGetSymbolAddress((void**)&xla, g_xla);
    cudaGetSymbolAddress((void**)&xhs, g_xhs);
    cudaGetSymbolAddress((void**)&xls, g_xls);
    cudaGetSymbolAddress((void**)&yhp, g_yhp);
    cudaGetSymbolAddress((void**)&ylp, g_ylp);
    cudaGetSymbolAddress((void**)&yha, g_yha);
    cudaGetSymbolAddress((void**)&yla, g_yla);
    cudaGetSymbolAddress((void**)&yhs, g_yhs);
    cudaGetSymbolAddress((void**)&yls, g_yls);
    cudaGetSymbolAddress((void**)&aggh, g_aggh);
    cudaGetSymbolAddress((void**)&aggl, g_aggl);
    cudaGetSymbolAddress((void**)&wlh, g_wlh);
    cudaGetSymbolAddress((void**)&wll, g_wll);
    cudaGetSymbolAddress((void**)&wrh, g_wrh);
    cudaGetSymbolAddress((void**)&wrl, g_wrl);
    cudaGetSymbolAddress((void**)&p1h, g_p1h);
    cudaGetSymbolAddress((void**)&p1l, g_p1l);
    cudaGetSymbolAddress((void**)&p2h, g_p2h);
    cudaGetSymbolAddress((void**)&p2l, g_p2l);

    // opt-in dynamic smem for every GEMM instantiation used
    cudaFuncSetAttribute(k_gemm<true,  false, false, false, 0>, cudaFuncAttributeMaxDynamicSharedMemorySize, GSMEM_BYTES);
    cudaFuncSetAttribute(k_gemm<false, true,  true,  true,  1>, cudaFuncAttributeMaxDynamicSharedMemorySize, GSMEM_BYTES);
    cudaFuncSetAttribute(k_gemm<false, true,  true,  true,  2>, cudaFuncAttributeMaxDynamicSharedMemorySize, GSMEM_BYTES);
    cudaFuncSetAttribute(k_gemm<false, true,  true,  true,  3>, cudaFuncAttributeMaxDynamicSharedMemorySize, GSMEM_BYTES);
    cudaFuncSetAttribute(k_gemm<true,  true,  true,  false, 1>, cudaFuncAttributeMaxDynamicSharedMemorySize, GSMEM_BYTES);
    cudaFuncSetAttribute(k_gemm<true,  true,  true,  false, 2>, cudaFuncAttributeMaxDynamicSharedMemorySize, GSMEM_BYTES);
    cudaFuncSetAttribute(k_gemm<true,  true,  true,  false, 3>, cudaFuncAttributeMaxDynamicSharedMemorySize, GSMEM_BYTES);
    cudaFuncSetAttribute(k_gemm<true,  false, true,  false, 4>, cudaFuncAttributeMaxDynamicSharedMemorySize, GSMEM_BYTES);
    cudaFuncSetAttribute(k_gemm<true,  false, true,  false, 1>, cudaFuncAttributeMaxDynamicSharedMemorySize, GSMEM_BYTES);

    // relation meta: type ids: 0=perf,1=artist,2=song
    int Ndst[6] = {NPn, NSn, NSn, NAn, NPn, NAn};
    int dstT[6] = {0, 2, 2, 1, 0, 1};
    int srcT[6] = {1, 0, 1, 0, 2, 2};
    bool pre[6] = {true, false, true, false, true, false};
    size_t tmpoff[6] = {0, 0, (size_t)NAn * DD, 0, (size_t)2 * NAn * DD, 0};
    int roff[6], eoff[6];
    int rsum = 0;
    {
        int o = 0;
        for (int r = 0; r < 6; r++) { roff[r] = o; o += Ndst[r]; }
        rsum = o;
        o = 0;
        for (int r = 0; r < 6; r++) { eoff[r] = o; o += Ecnt[r]; }
    }

    float* X[3] = {xp, xa, xs};
    float* Y[3] = {yp, ya, ys};
    uint32_t* XH[3] = {xhp, xha, xhs};
    uint32_t* XL[3] = {xlp, xla, xls};
    uint32_t* YH[3] = {yhp, yha, yhs};
    uint32_t* YL[3] = {ylp, yla, yls};
    int Nt[3] = {NPn, NAn, NSn};

    // launch 0: weight split; 1-3: gathers; 4-6: hoisted layer-0 pre-GEMMs (ncu slot)
    k_wsplit<<<1344, 256>>>(Wl, Wr, pw1, pw2, wlh, wll, wrh, wrl, p1h, p1l, p2h, p2l);
    k_gather<<<(NPn * 32 + 255) / 256, 256>>>(embP, nidP, xp, xhp, xlp, NPn);
    k_gather<<<(NAn * 32 + 255) / 256, 256>>>(embA, nidA, xa, xha, xla, NAn);
    k_gather<<<(NSn * 32 + 255) / 256, 256>>>(embS, nidS, xs, xhs, xls, NSn);
    {
        int prerels[3] = {0, 2, 4};
        for (int i = 0; i < 3; i++) {
            int r = prerels[i];
            int st = srcT[r];
            int Ns = Nt[st];
            size_t woff = (size_t)(0 * 6 + r) * 8192;
            k_gemm<true, false, false, false, 0><<<(Ns + 127) / 128, 256, GSMEM_BYTES>>>(
                XH[st], XL[st], wlh + woff, wll + woff, nullptr, nullptr, nullptr, nullptr,
                nullptr, nullptr, tmp + tmpoff[r], nullptr, nullptr, Ns);
        }
    }

    // build CSR per relation (layer-invariant)
    k_zero<<<(rsum + 255) / 256, 256>>>(cnt, rsum);
    k_zero<<<(rsum + 255) / 256, 256>>>(cursor, rsum);
    for (int r = 0; r < 6; r++) {
        int Nd = Ndst[r], E = Ecnt[r];
        const int* srcp = Eptr[r];
        const int* dstp = Eptr[r] + E;
        int nb = (Nd + 511) / 512;
        k_count<<<(E + 255) / 256, 256>>>(dstp, E, cnt + roff[r]);
        k_scan1<<<nb, 512>>>(cnt + roff[r], rowptr + roff[r], part, Nd);
        k_scan2<<<1, 512>>>(part, nb);
        k_scan3<<<(Nd + 255) / 256, 256>>>(rowptr + roff[r], part, Nd);
        k_scatter<<<(E + 255) / 256, 256>>>(srcp, dstp, E, rowptr + roff[r], cursor + roff[r],
                                            srcs + eoff[r]);
    }

    int order[6] = {0, 4, 1, 2, 3, 5};

    for (int layer = 0; layer < 3; layer++) {
        bool relu = (layer < 2);
        for (int oi = 0; oi < 6; oi++) {
            int r = order[oi];
            bool isFirst = (oi % 2 == 0);
            int Nd = Ndst[r];
            int st = srcT[r], dt = dstT[r];
            int Ns = Nt[st];
            size_t woff = (size_t)(layer * 6 + r) * 8192;
            const float* blr = bl + ((size_t)layer * 6 + r) * 128;
            int gb = (Nd + 127) / 128;
            int ab = (Nd * 32 + 255) / 256;
            if (pre[r]) {
                float* tsl = (layer == 0) ? (tmp + tmpoff[r]) : tmp;
                if (layer != 0) {
                    k_gemm<true, false, false, false, 0><<<(Ns + 127) / 128, 256, GSMEM_BYTES>>>(
                        XH[st], XL[st], wlh + woff, wll + woff, nullptr, nullptr, nullptr,
                        nullptr, nullptr, nullptr, tsl, nullptr, nullptr, Ns);
                }
                k_agg<false><<<ab, 256>>>(tsl, rowptr + roff[r], cnt + roff[r], srcs + eoff[r],
                                          agg, nullptr, nullptr, Nd);
                if (isFirst)
                    k_gemm<false, true, true, true, 1><<<gb, 256, GSMEM_BYTES>>>(
                        nullptr, nullptr, nullptr, nullptr, XH[dt], XL[dt], wrh + woff,
                        wrl + woff, blr, agg, Y[dt], YH[dt], YL[dt], Nd);
                else if (relu)
                    k_gemm<false, true, true, true, 3><<<gb, 256, GSMEM_BYTES>>>(
                        nullptr, nullptr, nullptr, nullptr, XH[dt], XL[dt], wrh + woff,
                        wrl + woff, blr, agg, Y[dt], YH[dt], YL[dt], Nd);
                else
                    k_gemm<false, true, true, true, 2><<<gb, 256, GSMEM_BYTES>>>(
                        nullptr, nullptr, nullptr, nullptr, XH[dt], XL[dt], wrh + woff,
                        wrl + woff, blr, agg, Y[dt], YH[dt], YL[dt], Nd);
            } else {
                k_agg<true><<<ab, 256>>>(X[st], rowptr + roff[r], cnt + roff[r], srcs + eoff[r],
                                         agg, aggh, aggl, Nd);
                if (isFirst)
                    k_gemm<true, true, true, false, 1><<<gb, 256, GSMEM_BYTES>>>(
                        aggh, aggl, wlh + woff, wll + woff, XH[dt], XL[dt], wrh + woff,
                        wrl + woff, blr, nullptr, Y[dt], YH[dt], YL[dt], Nd);
                else if (relu)
                    k_gemm<true, true, true, false, 3><<<gb, 256, GSMEM_BYTES>>>(
                        aggh, aggl, wlh + woff, wll + woff, XH[dt], XL[dt], wrh + woff,
                        wrl + woff, blr, nullptr, Y[dt], YH[dt], YL[dt], Nd);
                else
                    k_gemm<true, true, true, false, 2><<<gb, 256, GSMEM_BYTES>>>(
                        aggh, aggl, wlh + woff, wll + woff, XH[dt], XL[dt], wrh + woff,
                        wrl + woff, blr, nullptr, Y[dt], YH[dt], YL[dt], Nd);
            }
        }
        for (int t = 0; t < 3; t++) {
            float* z = X[t]; X[t] = Y[t]; Y[t] = z;
            uint32_t* zh = XH[t]; XH[t] = YH[t]; YH[t] = zh;
            uint32_t* zl = XL[t]; XL[t] = YL[t]; YL[t] = zl;
        }
    }

    // projection head per type; output order: performance, artist, song
    float* outp = (float*)d_out;
    float* outsec[3] = {outp, outp + (size_t)NPn * 128, outp + (size_t)(NPn + NAn) * 128};
    for (int t = 0; t < 3; t++) {
        int N = Nt[t];
        // LN writes hi/lo into the (dead) Y hi/lo planes
        k_ln<<<(N * 32 + 255) / 256, 256>>>(X[t], lng + t * 128, lnb + t * 128, YH[t], YL[t], N);
        k_gemm<true, false, true, false, 4><<<(N + 127) / 128, 256, GSMEM_BYTES>>>(
            YH[t], YL[t], p1h + (size_t)t * 8192, p1l + (size_t)t * 8192, nullptr, nullptr,
            nullptr, nullptr, pb1 + t * 128, nullptr, nullptr, aggh, aggl, N);
        k_gemm<true, false, true, false, 1><<<(N + 127) / 128, 256, GSMEM_BYTES>>>(
            aggh, aggl, p2h + (size_t)t * 8192, p2l + (size_t)t * 8192, nullptr, nullptr,
            nullptr, nullptr, pb2 + t * 128, nullptr, outsec[t], nullptr, nullptr, N);
    }
}

// round 15
// speedup vs baseline: 1.0517x; 1.0517x over previous
#include <cuda_runtime.h>
#include <cuda_bf16.h>
#include <math.h>
#include <stdint.h>

#define DD 128

static const int MAXP = 200000;
static const int MAXA = 30000;
static const int MAXS = 50000;
static const int MAXTMP = 110000;     // 30k (r0) + 30k (r2) + 50k (r4) slices
static const int MAXE_TOT = 2000000;
static const int MAXN_TOT = 560000 + 64;

// ---------------- scratch (static __device__, no allocations) ----------------
__device__ float g_xp[MAXP * DD];
__device__ float g_xa[MAXA * DD];
__device__ float g_xs[MAXS * DD];
__device__ float g_yp[MAXP * DD];
__device__ float g_ya[MAXA * DD];
__device__ float g_ys[MAXS * DD];
__device__ float g_agg[MAXP * DD];
__device__ float g_tmp[MAXTMP * DD];
__device__ int g_rowptr[MAXN_TOT];
__device__ int g_cnt[MAXN_TOT];
__device__ int g_cursor[MAXN_TOT];
__device__ int g_srcs[MAXE_TOT];
__device__ int g_part[1024];
// packed bf16x2 hi/lo weights: per 128x128 matrix -> 64 pair-rows x 128 cols uint32
__device__ uint32_t g_wlh[18 * 8192];
__device__ uint32_t g_wll[18 * 8192];
__device__ uint32_t g_wrh[18 * 8192];
__device__ uint32_t g_wrl[18 * 8192];
__device__ uint32_t g_p1h[3 * 8192];
__device__ uint32_t g_p1l[3 * 8192];
__device__ uint32_t g_p2h[3 * 8192];
__device__ uint32_t g_p2l[3 * 8192];

// ---------------- helpers ----------------
__device__ __forceinline__ float4 ld4(const float* p) { return *reinterpret_cast<const float4*>(p); }
__device__ __forceinline__ void st4(float* p, float4 v) { *reinterpret_cast<float4*>(p) = v; }
__device__ __forceinline__ float2 ld2(const float* p) { return *reinterpret_cast<const float2*>(p); }
__device__ __forceinline__ void st2(float* p, float2 v) { *reinterpret_cast<float2*>(p) = v; }
__device__ __forceinline__ float4 f4add(float4 a, float4 b) {
    return make_float4(a.x + b.x, a.y + b.y, a.z + b.z, a.w + b.w);
}

// pack two floats into bf16x2 (lower16 = first/even-k element)
__device__ __forceinline__ uint32_t pack_bf16x2(float lo_elem, float hi_elem) {
    uint32_t d;
    asm("cvt.rn.bf16x2.f32 %0, %1, %2;" : "=r"(d) : "f"(hi_elem), "f"(lo_elem));
    return d;
}
__device__ __forceinline__ void split_bf16(float a, float& hi, float& lo) {
    __nv_bfloat16 h = __float2bfloat16_rn(a);
    hi = __bfloat162float(h);
    lo = a - hi;
}

__device__ __forceinline__ void mma_bf16(float* c, const uint32_t* a, const uint32_t* b) {
    asm volatile(
        "mma.sync.aligned.m16n8k16.row.col.f32.bf16.bf16.f32 "
        "{%0,%1,%2,%3}, {%4,%5,%6,%7}, {%8,%9}, {%0,%1,%2,%3};"
        : "+f"(c[0]), "+f"(c[1]), "+f"(c[2]), "+f"(c[3])
        : "r"(a[0]), "r"(a[1]), "r"(a[2]), "r"(a[3]), "r"(b[0]), "r"(b[1]));
}

__device__ __forceinline__ void cp16(uint32_t* smem_dst, const uint32_t* gsrc) {
    uint32_t saddr = (uint32_t)__cvta_generic_to_shared(smem_dst);
    asm volatile("cp.async.ca.shared.global [%0], [%1], 16;" :: "r"(saddr), "l"(gsrc));
}
#define CP_COMMIT() asm volatile("cp.async.commit_group;")
#define CP_WAIT0() asm volatile("cp.async.wait_group 0;" ::: "memory")

// ---------------- utility kernels ----------------
__global__ void k_zero(int* p, int n) {
    int i = blockIdx.x * blockDim.x + threadIdx.x;
    if (i < n) p[i] = 0;
}

// convert all weight matrices to packed bf16x2 hi/lo (one launch)
__global__ void k_wsplit(const float* __restrict__ Wl, const float* __restrict__ Wr,
                         const float* __restrict__ p1, const float* __restrict__ p2,
                         uint32_t* wlh, uint32_t* wll, uint32_t* wrh, uint32_t* wrl,
                         uint32_t* p1h, uint32_t* p1l, uint32_t* p2h, uint32_t* p2l) {
    int idx = blockIdx.x * blockDim.x + threadIdx.x;
    const int NW = 18 * 8192, NP = 3 * 8192;
    const float* src;
    uint32_t *dh, *dl;
    int j;
    if (idx < NW) { src = Wl; dh = wlh; dl = wll; j = idx; }
    else if (idx < 2 * NW) { src = Wr; dh = wrh; dl = wrl; j = idx - NW; }
    else if (idx < 2 * NW + NP) { src = p1; dh = p1h; dl = p1l; j = idx - 2 * NW; }
    else if (idx < 2 * NW + 2 * NP) { src = p2; dh = p2h; dl = p2l; j = idx - 2 * NW - NP; }
    else return;
    int mat = j >> 13;
    int rem = j & 8191;
    int p = rem >> 7, n = rem & 127;
    float a = src[(size_t)mat * 16384 + (2 * p) * 128 + n];
    float b = src[(size_t)mat * 16384 + (2 * p + 1) * 128 + n];
    float ha, la, hb, lb;
    split_bf16(a, ha, la);
    split_bf16(b, hb, lb);
    dh[j] = pack_bf16x2(ha, hb);
    dl[j] = pack_bf16x2(la, lb);
}

__global__ void k_gather(const float* __restrict__ emb, const int* __restrict__ nid,
                         float* __restrict__ x, int n) {
    int i = blockIdx.x * blockDim.x + threadIdx.x;
    if (i < n * 32) {
        int r = i >> 5, c = i & 31;
        st4(x + (size_t)r * DD + c * 4, ld4(emb + (size_t)nid[r] * DD + c * 4));
    }
}

__global__ void k_count(const int* __restrict__ dst, int E, int* cnt) {
    int e = blockIdx.x * blockDim.x + threadIdx.x;
    if (e < E) atomicAdd(&cnt[dst[e]], 1);
}

__global__ void k_scan1(const int* __restrict__ cnt, int* __restrict__ rowptr,
                        int* __restrict__ part, int N) {
    __shared__ int s[512];
    int tid = threadIdx.x;
    int i = blockIdx.x * 512 + tid;
    int v = (i < N) ? cnt[i] : 0;
    s[tid] = v;
    __syncthreads();
    for (int off = 1; off < 512; off <<= 1) {
        int t = (tid >= off) ? s[tid - off] : 0;
        __syncthreads();
        s[tid] += t;
        __syncthreads();
    }
    if (i < N) rowptr[i] = s[tid] - v;
    if (tid == 511) part[blockIdx.x] = s[511];
}

__global__ void k_scan2(int* part, int n) {
    __shared__ int s[512];
    int tid = threadIdx.x;
    int v = (tid < n) ? part[tid] : 0;
    s[tid] = v;
    __syncthreads();
    for (int off = 1; off < 512; off <<= 1) {
        int t = (tid >= off) ? s[tid - off] : 0;
        __syncthreads();
        s[tid] += t;
        __syncthreads();
    }
    if (tid < n) part[tid] = s[tid] - v;
}

__global__ void k_scan3(int* rowptr, const int* __restrict__ part, int N) {
    int i = blockIdx.x * blockDim.x + threadIdx.x;
    if (i < N) rowptr[i] += part[i >> 9];
}

__global__ void k_scatter(const int* __restrict__ src, const int* __restrict__ dst, int E,
                          const int* __restrict__ rowptr, int* __restrict__ cursor,
                          int* __restrict__ out) {
    int e = blockIdx.x * blockDim.x + threadIdx.x;
    if (e < E) {
        int d = dst[e];
        int pos = rowptr[d] + atomicAdd(&cursor[d], 1);
        out[pos] = src[e];
    }
}

// segment-mean gather: one warp per destination row
__global__ void k_agg(const float* __restrict__ feat, const int* __restrict__ rowptr,
                      const int* __restrict__ cnt, const int* __restrict__ srcs,
                      float* __restrict__ out, int N) {
    int warp = (blockIdx.x * blockDim.x + threadIdx.x) >> 5;
    if (warp >= N) return;
    int lane = threadIdx.x & 31;
    int beg = rowptr[warp], n = cnt[warp];
    float4 acc = make_float4(0.f, 0.f, 0.f, 0.f);
    int i = 0;
    for (; i + 4 <= n; i += 4) {
        int s0 = srcs[beg + i], s1 = srcs[beg + i + 1];
        int s2 = srcs[beg + i + 2], s3 = srcs[beg + i + 3];
        float4 v0 = ld4(feat + (size_t)s0 * DD + lane * 4);
        float4 v1 = ld4(feat + (size_t)s1 * DD + lane * 4);
        float4 v2 = ld4(feat + (size_t)s2 * DD + lane * 4);
        float4 v3 = ld4(feat + (size_t)s3 * DD + lane * 4);
        acc = f4add(acc, f4add(f4add(v0, v1), f4add(v2, v3)));
    }
    for (; i < n; i++) {
        int s = srcs[beg + i];
        acc = f4add(acc, ld4(feat + (size_t)s * DD + lane * 4));
    }
    float inv = 1.0f / (float)max(n, 1);
    acc.x *= inv; acc.y *= inv; acc.z *= inv; acc.w *= inv;
    st4(out + (size_t)warp * DD + lane * 4, acc);
}

// layernorm: one warp per row
__global__ void k_ln(const float* __restrict__ x, const float* __restrict__ g,
                     const float* __restrict__ b, float* __restrict__ y, int N) {
    int warp = (blockIdx.x * blockDim.x + threadIdx.x) >> 5;
    if (warp >= N) return;
    int lane = threadIdx.x & 31;
    float4 v = ld4(x + (size_t)warp * DD + lane * 4);
    float s = v.x + v.y + v.z + v.w;
#pragma unroll
    for (int m = 16; m > 0; m >>= 1) s += __shfl_xor_sync(0xffffffffu, s, m);
    float mu = s * (1.0f / 128.0f);
    float4 d = make_float4(v.x - mu, v.y - mu, v.z - mu, v.w - mu);
    float ss = d.x * d.x + d.y * d.y + d.z * d.z + d.w * d.w;
#pragma unroll
    for (int m = 16; m > 0; m >>= 1) ss += __shfl_xor_sync(0xffffffffu, ss, m);
    float sc = rsqrtf(ss * (1.0f / 128.0f) + 1e-5f);
    float4 gv = ld4(g + lane * 4), bv = ld4(b + lane * 4);
    float4 o = make_float4(d.x * sc * gv.x + bv.x, d.y * sc * gv.y + bv.y,
                           d.z * sc * gv.z + bv.z, d.w * sc * gv.w + bv.w);
    st4(y + (size_t)warp * DD + lane * 4, o);
}

// ---------------- tensor-core fused GEMM (3xBF16 m16n8k16, W pre-split + cp.async) ------
// h = (U1 ? A1@W1 : 0) + (U2 ? A2@W2 : 0) + (HASPASS ? pass : 0) + (HASB ? bias : 0)
// EPI: 0 store; 1 l2norm store; 2 l2norm add; 3 l2norm add relu; 4 relu store
// A fp32 (split in-kernel); W packed bf16x2 hi/lo [64 pair-rows][128] loaded via cp.async.
// Block 128x128, 8 warps (2m x 4n), warp tile 64x32, k16 chunks, 2 smem buffers.
template <bool U1, bool U2, bool HASB, bool HASPASS, int EPI>
__global__ void __launch_bounds__(256, 2)
k_gemm(const float* __restrict__ A1,
       const uint32_t* __restrict__ W1h, const uint32_t* __restrict__ W1l,
       const float* __restrict__ A2,
       const uint32_t* __restrict__ W2h, const uint32_t* __restrict__ W2l,
       const float* __restrict__ bias, const float* __restrict__ pass,
       float* __restrict__ out, int N) {
    __shared__ uint32_t sAhi[2][128 * 12];
    __shared__ uint32_t sAlo[2][128 * 12];
    __shared__ uint32_t sWhi[2][8 * 136];
    __shared__ uint32_t sWlo[2][8 * 136];
    __shared__ float red[4 * 128];

    const int tid = threadIdx.x;
    const int warp = tid >> 5;
    const int lane = tid & 31;
    const int warpM = warp >> 2;
    const int warpN = warp & 3;
    const int g = lane >> 2;
    const int t = lane & 3;
    const int row0 = blockIdx.x * 128;

    const int aR = tid >> 1, aH = tid & 1;   // A: row, k-half
    const int wP = tid >> 5, wC = tid & 31;  // W: pair-row, col quad
    const int aRow = row0 + aR;

    float Cr[4][4][4];
#pragma unroll
    for (int mt = 0; mt < 4; mt++)
#pragma unroll
        for (int nt = 0; nt < 4; nt++)
#pragma unroll
            for (int j = 0; j < 4; j++) Cr[mt][nt][j] = 0.f;

#pragma unroll
    for (int s = 0; s < 2; s++) {
        if ((s == 0 && !U1) || (s == 1 && !U2)) continue;
        const float* Ap = (s == 0) ? A1 : A2;
        const uint32_t* Wph = (s == 0) ? W1h : W2h;
        const uint32_t* Wpl = (s == 0) ? W1l : W2l;

        auto issueW = [&](int buf, int c) {
            cp16(&sWhi[buf][wP * 136 + wC * 4], Wph + (size_t)(c * 8 + wP) * 128 + wC * 4);
            cp16(&sWlo[buf][wP * 136 + wC * 4], Wpl + (size_t)(c * 8 + wP) * 128 + wC * 4);
        };
        auto loadA = [&](int c, float4& va0, float4& va1) {
            va0 = make_float4(0.f, 0.f, 0.f, 0.f);
            va1 = make_float4(0.f, 0.f, 0.f, 0.f);
            if (aRow < N) {
                va0 = ld4(Ap + (size_t)aRow * 128 + c * 16 + aH * 8);
                va1 = ld4(Ap + (size_t)aRow * 128 + c * 16 + aH * 8 + 4);
            }
        };
        auto stageA = [&](int buf, float4 va0, float4 va1) {
            float h0, l0, h1, l1;
            uint4 ph, pl;
            split_bf16(va0.x, h0, l0); split_bf16(va0.y, h1, l1);
            ph.x = pack_bf16x2(h0, h1); pl.x = pack_bf16x2(l0, l1);
            split_bf16(va0.z, h0, l0); split_bf16(va0.w, h1, l1);
            ph.y = pack_bf16x2(h0, h1); pl.y = pack_bf16x2(l0, l1);
            split_bf16(va1.x, h0, l0); split_bf16(va1.y, h1, l1);
            ph.z = pack_bf16x2(h0, h1); pl.z = pack_bf16x2(l0, l1);
            split_bf16(va1.z, h0, l0); split_bf16(va1.w, h1, l1);
            ph.w = pack_bf16x2(h0, h1); pl.w = pack_bf16x2(l0, l1);
            *reinterpret_cast<uint4*>(&sAhi[buf][aR * 12 + aH * 4]) = ph;
            *reinterpret_cast<uint4*>(&sAlo[buf][aR * 12 + aH * 4]) = pl;
        };

        // prologue: chunk 0 into buffer 0 (W async, A split)
        {
            issueW(0, 0);
            CP_COMMIT();
            float4 va0, va1;
            loadA(0, va0, va1);
            stageA(0, va0, va1);
        }

        for (int c = 0; c < 8; c++) {
            CP_WAIT0();
            __syncthreads();
            const int cur = c & 1;
            const int nxt = cur ^ 1;
            bool haveNext = (c + 1 < 8);
            float4 va0, va1;
            if (haveNext) {
                issueW(nxt, c + 1);
                CP_COMMIT();
                loadA(c + 1, va0, va1);
            }

            // compute on current buffer (one k16 step)
            {
                uint32_t bHi[4][2], bLo[4][2];
#pragma unroll
                for (int nt = 0; nt < 4; nt++) {
                    int n0 = warpN * 32 + nt * 8 + g;
                    bHi[nt][0] = sWhi[cur][t * 136 + n0];
                    bHi[nt][1] = sWhi[cur][(t + 4) * 136 + n0];
                    bLo[nt][0] = sWlo[cur][t * 136 + n0];
                    bLo[nt][1] = sWlo[cur][(t + 4) * 136 + n0];
                }
#pragma unroll
                for (int mt = 0; mt < 4; mt++) {
                    int rb = warpM * 64 + mt * 16 + g;
                    uint32_t aHi[4], aLo[4];
                    aHi[0] = sAhi[cur][rb * 12 + t];
                    aHi[1] = sAhi[cur][(rb + 8) * 12 + t];
                    aHi[2] = sAhi[cur][rb * 12 + t + 4];
                    aHi[3] = sAhi[cur][(rb + 8) * 12 + t + 4];
                    aLo[0] = sAlo[cur][rb * 12 + t];
                    aLo[1] = sAlo[cur][(rb + 8) * 12 + t];
                    aLo[2] = sAlo[cur][rb * 12 + t + 4];
                    aLo[3] = sAlo[cur][(rb + 8) * 12 + t + 4];
#pragma unroll
                    for (int nt = 0; nt < 4; nt++) {
                        mma_bf16(Cr[mt][nt], aHi, bHi[nt]);
                        mma_bf16(Cr[mt][nt], aLo, bHi[nt]);
                        mma_bf16(Cr[mt][nt], aHi, bLo[nt]);
                    }
                }
            }

            if (haveNext) stageA(nxt, va0, va1);
        }
        __syncthreads();  // drain before next source overwrites buffer 0
    }

    // ---- epilogue ----
    float2 bv[4];
    if constexpr (HASB) {
#pragma unroll
        for (int nt = 0; nt < 4; nt++) bv[nt] = ld2(bias + warpN * 32 + nt * 8 + 2 * t);
    }

#pragma unroll
    for (int mt = 0; mt < 4; mt++) {
        int gr0 = row0 + warpM * 64 + mt * 16 + g;
        int gr1 = gr0 + 8;
        bool v0 = gr0 < N, v1 = gr1 < N;
#pragma unroll
        for (int nt = 0; nt < 4; nt++) {
            int col = warpN * 32 + nt * 8 + 2 * t;
            if constexpr (HASPASS) {
                if (v0) {
                    float2 p = ld2(pass + (size_t)gr0 * 128 + col);
                    Cr[mt][nt][0] += p.x; Cr[mt][nt][1] += p.y;
                }
                if (v1) {
                    float2 p = ld2(pass + (size_t)gr1 * 128 + col);
                    Cr[mt][nt][2] += p.x; Cr[mt][nt][3] += p.y;
                }
            }
            if constexpr (HASB) {
                Cr[mt][nt][0] += bv[nt].x; Cr[mt][nt][1] += bv[nt].y;
                Cr[mt][nt][2] += bv[nt].x; Cr[mt][nt][3] += bv[nt].y;
            }
        }
    }

    if constexpr (EPI == 0 || EPI == 4) {
#pragma unroll
        for (int mt = 0; mt < 4; mt++) {
            int gr0 = row0 + warpM * 64 + mt * 16 + g;
            int gr1 = gr0 + 8;
#pragma unroll
            for (int nt = 0; nt < 4; nt++) {
                int col = warpN * 32 + nt * 8 + 2 * t;
                float2 u0 = make_float2(Cr[mt][nt][0], Cr[mt][nt][1]);
                float2 u1 = make_float2(Cr[mt][nt][2], Cr[mt][nt][3]);
                if constexpr (EPI == 4) {
                    u0.x = fmaxf(u0.x, 0.f); u0.y = fmaxf(u0.y, 0.f);
                    u1.x = fmaxf(u1.x, 0.f); u1.y = fmaxf(u1.y, 0.f);
                }
                if (gr0 < N) st2(out + (size_t)gr0 * 128 + col, u0);
                if (gr1 < N) st2(out + (size_t)gr1 * 128 + col, u1);
            }
        }
    } else {
#pragma unroll
        for (int mt = 0; mt < 4; mt++) {
            float s0 = 0.f, s1 = 0.f;
#pragma unroll
            for (int nt = 0; nt < 4; nt++) {
                s0 += Cr[mt][nt][0] * Cr[mt][nt][0] + Cr[mt][nt][1] * Cr[mt][nt][1];
                s1 += Cr[mt][nt][2] * Cr[mt][nt][2] + Cr[mt][nt][3] * Cr[mt][nt][3];
            }
            s0 += __shfl_xor_sync(0xffffffffu, s0, 1);
            s0 += __shfl_xor_sync(0xffffffffu, s0, 2);
            s1 += __shfl_xor_sync(0xffffffffu, s1, 1);
            s1 += __shfl_xor_sync(0xffffffffu, s1, 2);
            if (t == 0) {
                int lr = warpM * 64 + mt * 16 + g;
                red[warpN * 128 + lr] = s0;
                red[warpN * 128 + lr + 8] = s1;
            }
        }
        __syncthreads();
#pragma unroll
        for (int mt = 0; mt < 4; mt++) {
            int lr0 = warpM * 64 + mt * 16 + g;
            int lr1 = lr0 + 8;
            float q0 = red[lr0] + red[128 + lr0] + red[256 + lr0] + red[384 + lr0];
            float q1 = red[lr1] + red[128 + lr1] + red[256 + lr1] + red[384 + lr1];
            float sc0 = 1.0f / fmaxf(sqrtf(q0), 1e-12f);
            float sc1 = 1.0f / fmaxf(sqrtf(q1), 1e-12f);
            int gr0 = row0 + lr0, gr1 = row0 + lr1;
#pragma unroll
            for (int nt = 0; nt < 4; nt++) {
                int col = warpN * 32 + nt * 8 + 2 * t;
                float2 u0 = make_float2(Cr[mt][nt][0] * sc0, Cr[mt][nt][1] * sc0);
                float2 u1 = make_float2(Cr[mt][nt][2] * sc1, Cr[mt][nt][3] * sc1);
                if constexpr (EPI == 2 || EPI == 3) {
                    if (gr0 < N) {
                        float2 p = ld2(out + (size_t)gr0 * 128 + col);
                        u0.x += p.x; u0.y += p.y;
                    }
                    if (gr1 < N) {
                        float2 p = ld2(out + (size_t)gr1 * 128 + col);
                        u1.x += p.x; u1.y += p.y;
                    }
                    if constexpr (EPI == 3) {
                        u0.x = fmaxf(u0.x, 0.f); u0.y = fmaxf(u0.y, 0.f);
                        u1.x = fmaxf(u1.x, 0.f); u1.y = fmaxf(u1.y, 0.f);
                    }
                }
                if (gr0 < N) st2(out + (size_t)gr0 * 128 + col, u0);
                if (gr1 < N) st2(out + (size_t)gr1 * 128 + col, u1);
            }
        }
    }
}

// ---------------- host orchestration ----------------
extern "C" void kernel_launch(void* const* d_in, const int* in_sizes, int n_in,
                              void* d_out, int out_size) {
    const int* nidP = (const int*)d_in[0];
    const int* nidA = (const int*)d_in[1];
    const int* nidS = (const int*)d_in[2];
    const int* Eptr[6];
    int Ecnt[6];
    for (int r = 0; r < 6; r++) {
        Eptr[r] = (const int*)d_in[3 + r];
        Ecnt[r] = in_sizes[3 + r] / 2;
    }
    const float* embP = (const float*)d_in[9];
    const float* embA = (const float*)d_in[10];
    const float* embS = (const float*)d_in[11];
    const float* Wl = (const float*)d_in[12];
    const float* bl = (const float*)d_in[13];
    const float* Wr = (const float*)d_in[14];
    const float* lng = (const float*)d_in[15];
    const float* lnb = (const float*)d_in[16];
    const float* pw1 = (const float*)d_in[17];
    const float* pb1 = (const float*)d_in[18];
    const float* pw2 = (const float*)d_in[19];
    const float* pb2 = (const float*)d_in[20];
    int NPn = in_sizes[0], NAn = in_sizes[1], NSn = in_sizes[2];

    float *xp, *xa, *xs, *yp, *ya, *ys, *agg, *tmp;
    int *rowptr, *cnt, *cursor, *srcs, *part;
    uint32_t *wlh, *wll, *wrh, *wrl, *p1h, *p1l, *p2h, *p2l;
    cudaGetSymbolAddress((void**)&xp, g_xp);
    cudaGetSymbolAddress((void**)&xa, g_xa);
    cudaGetSymbolAddress((void**)&xs, g_xs);
    cudaGetSymbolAddress((void**)&yp, g_yp);
    cudaGetSymbolAddress((void**)&ya, g_ya);
    cudaGetSymbolAddress((void**)&ys, g_ys);
    cudaGetSymbolAddress((void**)&agg, g_agg);
    cudaGetSymbolAddress((void**)&tmp, g_tmp);
    cudaGetSymbolAddress((void**)&rowptr, g_rowptr);
    cudaGetSymbolAddress((void**)&cnt, g_cnt);
    cudaGetSymbolAddress((void**)&cursor, g_cursor);
    cudaGetSymbolAddress((void**)&srcs, g_srcs);
    cudaGetSymbolAddress((void**)&part, g_part);
    cudaGetSymbolAddress((void**)&wlh, g_wlh);
    cudaGetSymbolAddress((void**)&wll, g_wll);
    cudaGetSymbolAddress((void**)&wrh, g_wrh);
    cudaGetSymbolAddress((void**)&wrl, g_wrl);
    cudaGetSymbolAddress((void**)&p1h, g_p1h);
    cudaGetSymbolAddress((void**)&p1l, g_p1l);
    cudaGetSymbolAddress((void**)&p2h, g_p2h);
    cudaGetSymbolAddress((void**)&p2l, g_p2l);

    // relation meta: type ids: 0=perf,1=artist,2=song
    int Ndst[6] = {NPn, NSn, NSn, NAn, NPn, NAn};
    int dstT[6] = {0, 2, 2, 1, 0, 1};
    int srcT[6] = {1, 0, 1, 0, 2, 2};
    bool pre[6] = {true, false, true, false, true, false};
    size_t tmpoff[6] = {0, 0, (size_t)NAn * DD, 0, (size_t)2 * NAn * DD, 0};
    int roff[6], eoff[6];
    int rsum = 0;
    {
        int o = 0;
        for (int r = 0; r < 6; r++) { roff[r] = o; o += Ndst[r]; }
        rsum = o;
        o = 0;
        for (int r = 0; r < 6; r++) { eoff[r] = o; o += Ecnt[r]; }
    }

    float* X[3] = {xp, xa, xs};
    float* Y[3] = {yp, ya, ys};
    int Nt[3] = {NPn, NAn, NSn};

    // launches 0-2: gathers; 3: weight split; 4-6: hoisted layer-0 pre-GEMMs (ncu slot)
    k_gather<<<(NPn * 32 + 255) / 256, 256>>>(embP, nidP, xp, NPn);
    k_gather<<<(NAn * 32 + 255) / 256, 256>>>(embA, nidA, xa, NAn);
    k_gather<<<(NSn * 32 + 255) / 256, 256>>>(embS, nidS, xs, NSn);
    k_wsplit<<<1344, 256>>>(Wl, Wr, pw1, pw2, wlh, wll, wrh, wrl, p1h, p1l, p2h, p2l);
    {
        int prerels[3] = {0, 2, 4};
        for (int i = 0; i < 3; i++) {
            int r = prerels[i];
            int st = srcT[r];
            int Ns = Nt[st];
            size_t woff = (size_t)(0 * 6 + r) * 8192;
            k_gemm<true, false, false, false, 0><<<(Ns + 127) / 128, 256>>>(
                X[st], wlh + woff, wll + woff, nullptr, nullptr, nullptr,
                nullptr, nullptr, tmp + tmpoff[r], Ns);
        }
    }

    // build CSR per relation (layer-invariant)
    k_zero<<<(rsum + 255) / 256, 256>>>(cnt, rsum);
    k_zero<<<(rsum + 255) / 256, 256>>>(cursor, rsum);
    for (int r = 0; r < 6; r++) {
        int Nd = Ndst[r], E = Ecnt[r];
        const int* srcp = Eptr[r];
        const int* dstp = Eptr[r] + E;
        int nb = (Nd + 511) / 512;
        k_count<<<(E + 255) / 256, 256>>>(dstp, E, cnt + roff[r]);
        k_scan1<<<nb, 512>>>(cnt + roff[r], rowptr + roff[r], part, Nd);
        k_scan2<<<1, 512>>>(part, nb);
        k_scan3<<<(Nd + 255) / 256, 256>>>(rowptr + roff[r], part, Nd);
        k_scatter<<<(E + 255) / 256, 256>>>(srcp, dstp, E, rowptr + roff[r], cursor + roff[r],
                                            srcs + eoff[r]);
    }

    int order[6] = {0, 4, 1, 2, 3, 5};

    for (int layer = 0; layer < 3; layer++) {
        bool relu = (layer < 2);
        for (int oi = 0; oi < 6; oi++) {
            int r = order[oi];
            bool isFirst = (oi % 2 == 0);
            int Nd = Ndst[r];
            int st = srcT[r], dt = dstT[r];
            int Ns = Nt[st];
            size_t woff = (size_t)(layer * 6 + r) * 8192;
            const float* blr = bl + ((size_t)layer * 6 + r) * 128;
            int gb = (Nd + 127) / 128;
            int ab = (Nd * 32 + 255) / 256;
            if (pre[r]) {
                float* tsl = (layer == 0) ? (tmp + tmpoff[r]) : tmp;
                if (layer != 0) {
                    k_gemm<true, false, false, false, 0><<<(Ns + 127) / 128, 256>>>(
                        X[st], wlh + woff, wll + woff, nullptr, nullptr, nullptr,
                        nullptr, nullptr, tsl, Ns);
                }
                k_agg<<<ab, 256>>>(tsl, rowptr + roff[r], cnt + roff[r], srcs + eoff[r], agg, Nd);
                if (isFirst)
                    k_gemm<false, true, true, true, 1><<<gb, 256>>>(
                        nullptr, nullptr, nullptr, X[dt], wrh + woff, wrl + woff,
                        blr, agg, Y[dt], Nd);
                else if (relu)
                    k_gemm<false, true, true, true, 3><<<gb, 256>>>(
                        nullptr, nullptr, nullptr, X[dt], wrh + woff, wrl + woff,
                        blr, agg, Y[dt], Nd);
                else
                    k_gemm<false, true, true, true, 2><<<gb, 256>>>(
                        nullptr, nullptr, nullptr, X[dt], wrh + woff, wrl + woff,
                        blr, agg, Y[dt], Nd);
            } else {
                k_agg<<<ab, 256>>>(X[st], rowptr + roff[r], cnt + roff[r], srcs + eoff[r], agg, Nd);
                if (isFirst)
                    k_gemm<true, true, true, false, 1><<<gb, 256>>>(
                        agg, wlh + woff, wll + woff, X[dt], wrh + woff, wrl + woff,
                        blr, nullptr, Y[dt], Nd);
                else if (relu)
                    k_gemm<true, true, true, false, 3><<<gb, 256>>>(
                        agg, wlh + woff, wll + woff, X[dt], wrh + woff, wrl + woff,
                        blr, nullptr, Y[dt], Nd);
                else
                    k_gemm<true, true, true, false, 2><<<gb, 256>>>(
                        agg, wlh + woff, wll + woff, X[dt], wrh + woff, wrl + woff,
                        blr, nullptr, Y[dt], Nd);
            }
        }
        for (int t = 0; t < 3; t++) {
            float* z = X[t];
            X[t] = Y[t];
            Y[t] = z;
        }
    }

    // projection head per type; output order: performance, artist, song
    float* outp = (float*)d_out;
    float* outsec[3] = {outp, outp + (size_t)NPn * 128, outp + (size_t)(NPn + NAn) * 128};
    for (int t = 0; t < 3; t++) {
        int N = Nt[t];
        k_ln<<<(N * 32 + 255) / 256, 256>>>(X[t], lng + t * 128, lnb + t * 128, Y[t], N);
        k_gemm<true, false, true, false, 4><<<(N + 127) / 128, 256>>>(
            Y[t], p1h + (size_t)t * 8192, p1l + (size_t)t * 8192, nullptr, nullptr, nullptr,
            pb1 + t * 128, nullptr, agg, N);
        k_gemm<true, false, true, false, 1><<<(N + 127) / 128, 256>>>(
            agg, p2h + (size_t)t * 8192, p2l + (size_t)t * 8192, nullptr, nullptr, nullptr,
            pb2 + t * 128, nullptr, outsec[t], N);
    }
}